// round 11
// baseline (speedup 1.0000x reference)
#include <cuda_runtime.h>
#include <cuda_bf16.h>
#include <cuda_fp16.h>
#include <cstdint>

using bf16 = __nv_bfloat16;

#define DEVI __device__ __forceinline__

constexpr int Bc = 4;      // batch
constexpr int Nt = 2048;   // tokens
constexpr int Dc = 1024;   // model dim
constexpr int Fc = 4096;   // ffn dim
constexpr int Mrows = Bc * Nt;   // 8192
constexpr int KSPLIT = 4;        // GEMM2 split-K factor

// hybrid column split: SIMT (FMA-pipe) slice sizes
constexpr int SIMT_N1 = 512;              // GEMM1 cols done by SIMT
constexpr int TEN_N1  = Fc - SIMT_N1;     // 3584 -> 28 col-blocks
constexpr int SIMT_N2 = 128;              // GEMM2 cols done by SIMT
constexpr int TEN_N2  = Dc - SIMT_N2;     // 896 -> 7 col-blocks

constexpr int BM = 128, BN = 128, BK = 32;
constexpr int SA_ST   = BK + 8;    // 40
constexpr int SBKN_ST = BN + 8;    // 136
constexpr int NTHREADS = 256;

// ---------------- scratch ----------------------------------------------------
__device__ __align__(16) bf16   g_T[(size_t)Nt * Nt];
__device__ __align__(16) bf16   g_xb[(size_t)Bc * Nt * Dc];
__device__ __align__(16) float  g_y1[(size_t)Bc * Nt * Dc];
__device__ __align__(16) float  g_x1[(size_t)Bc * Nt * Dc];
__device__ __align__(16) __half g_x1h[(size_t)Bc * Nt * Dc];
__device__ __align__(16) __half g_W1h[(size_t)Fc * Dc];
__device__ __align__(16) __half g_W2h[(size_t)Dc * Fc];
__device__ __align__(16) __half g_H[(size_t)Bc * Nt * Fc];
__device__ __align__(16) float  g_p2[(size_t)KSPLIT * Mrows * Dc];  // split-K partials

// ---------------- PTX helpers -------------------------------------------------
DEVI uint32_t smem_u32(const void* p) {
    return static_cast<uint32_t>(__cvta_generic_to_shared(p));
}
DEVI void cp_async16(uint32_t sdst, const void* gsrc) {
    asm volatile("cp.async.cg.shared.global [%0], [%1], 16;\n" :: "r"(sdst), "l"(gsrc));
}
DEVI void cp_commit() { asm volatile("cp.async.commit_group;\n"); }
template <int N> DEVI void cp_wait() {
    asm volatile("cp.async.wait_group %0;\n" :: "n"(N));
}
DEVI void ldmx4(uint32_t& r0, uint32_t& r1, uint32_t& r2, uint32_t& r3, uint32_t a) {
    asm volatile("ldmatrix.sync.aligned.m8n8.x4.shared.b16 {%0,%1,%2,%3}, [%4];\n"
                 : "=r"(r0), "=r"(r1), "=r"(r2), "=r"(r3) : "r"(a));
}
DEVI void ldmx4t(uint32_t& r0, uint32_t& r1, uint32_t& r2, uint32_t& r3, uint32_t a) {
    asm volatile("ldmatrix.sync.aligned.m8n8.x4.trans.shared.b16 {%0,%1,%2,%3}, [%4];\n"
                 : "=r"(r0), "=r"(r1), "=r"(r2), "=r"(r3) : "r"(a));
}
DEVI void mma16816_bf(float c[4], const uint32_t a[4], const uint32_t b[2]) {
    asm volatile(
        "mma.sync.aligned.m16n8k16.row.col.f32.bf16.bf16.f32 "
        "{%0,%1,%2,%3}, {%4,%5,%6,%7}, {%8,%9}, {%0,%1,%2,%3};\n"
        : "+f"(c[0]), "+f"(c[1]), "+f"(c[2]), "+f"(c[3])
        : "r"(a[0]), "r"(a[1]), "r"(a[2]), "r"(a[3]), "r"(b[0]), "r"(b[1]));
}
DEVI void mma16816_hf32(float c[4], const uint32_t a[4], const uint32_t b[2]) {
    asm volatile(
        "mma.sync.aligned.m16n8k16.row.col.f32.f16.f16.f32 "
        "{%0,%1,%2,%3}, {%4,%5,%6,%7}, {%8,%9}, {%0,%1,%2,%3};\n"
        : "+f"(c[0]), "+f"(c[1]), "+f"(c[2]), "+f"(c[3])
        : "r"(a[0]), "r"(a[1]), "r"(a[2]), "r"(a[3]), "r"(b[0]), "r"(b[1]));
}
DEVI void mma16816_hf16(uint32_t c[2], const uint32_t a[4], const uint32_t b[2]) {
    asm volatile(
        "mma.sync.aligned.m16n8k16.row.col.f16.f16.f16.f16 "
        "{%0,%1}, {%2,%3,%4,%5}, {%6,%7}, {%0,%1};\n"
        : "+r"(c[0]), "+r"(c[1])
        : "r"(a[0]), "r"(a[1]), "r"(a[2]), "r"(a[3]), "r"(b[0]), "r"(b[1]));
}
DEVI float gelu_exact(float v) {
    return 0.5f * v * (1.0f + erff(v * 0.70710678118654752f));
}

// ---------------- prep kernels ----------------------------------------------
__global__ void cvt_x_kernel(const float* __restrict__ src, int n4)
{
    int i = blockIdx.x * blockDim.x + threadIdx.x;
    if (i < n4) {
        float4 v = reinterpret_cast<const float4*>(src)[i];
        __nv_bfloat162* d2 = reinterpret_cast<__nv_bfloat162*>(g_xb) + 2 * (size_t)i;
        d2[0] = __floats2bfloat162_rn(v.x, v.y);
        d2[1] = __floats2bfloat162_rn(v.z, v.w);
    }
}

__global__ void cvt_w_both_kernel(const float* __restrict__ W1,
                                  const float* __restrict__ W2, int n4each)
{
    int i = blockIdx.x * blockDim.x + threadIdx.x;
    const float* src;
    __half* dst;
    int idx;
    if (i < n4each)          { src = W1; dst = g_W1h; idx = i; }
    else if (i < 2 * n4each) { src = W2; dst = g_W2h; idx = i - n4each; }
    else return;
    float4 v = reinterpret_cast<const float4*>(src)[idx];
    __half2* d2 = reinterpret_cast<__half2*>(dst) + 2 * (size_t)idx;
    d2[0] = __floats2half2_rn(v.x, v.y);
    d2[1] = __floats2half2_rn(v.z, v.w);
}

__global__ void buildT_kernel(const float* __restrict__ w)
{
    int i = blockIdx.x * blockDim.x + threadIdx.x;
    int n = i >> 11;
    int m = i & (Nt - 1);
    float v = (m <= n) ? w[n - m] : 0.0f;
    g_T[i] = __float2bfloat16(v);
}

// ---------------- conv GEMM (bf16, f32 acc, PAIR-BALANCED triangular) ----------
__global__ void __launch_bounds__(NTHREADS, 2) conv_gemm_kernel(
    const float* __restrict__ x, const float* __restrict__ scale)
{
    constexpr int K = Nt;
    constexpr int Nc = Dc;

    const bf16* __restrict__ A  = g_T;
    const bf16* __restrict__ Bp = g_xb + (size_t)blockIdx.z * Nt * Dc;

    __shared__ __align__(16) bf16 sA[2][BM * SA_ST];
    __shared__ __align__(16) bf16 sB[2][BK * SBKN_ST];

    const int tid  = threadIdx.x;
    const int pair = blockIdx.y;
    const int bn0  = blockIdx.x * BN;
    const int wid  = tid >> 5;
    const int lane = tid & 31;
    const int wm   = (wid & 3) * 32;
    const int wn   = (wid >> 2) * 64;

#pragma unroll
    for (int half = 0; half < 2; half++) {
        const int ybm  = (half == 0) ? (15 - pair) : pair;
        const int bm0  = ybm * BM;
        const int kmax = 4 * (ybm + 1);

        float acc[2][8][4];
#pragma unroll
        for (int i = 0; i < 2; i++)
#pragma unroll
            for (int j = 0; j < 8; j++)
#pragma unroll
                for (int q = 0; q < 4; q++) acc[i][j][q] = 0.0f;

        auto load_tiles = [&](int s, int kt) {
            const bf16* Ag = A + (size_t)bm0 * K + (size_t)kt * BK;
#pragma unroll
            for (int i = 0; i < 2; i++) {
                int ch  = tid + i * NTHREADS;
                int row = ch >> 2;
                int col = (ch & 3) * 8;
                cp_async16(smem_u32(&sA[s][row * SA_ST + col]),
                           Ag + (size_t)row * K + col);
            }
            const bf16* Bg = Bp + (size_t)(kt * BK) * Nc + bn0;
#pragma unroll
            for (int i = 0; i < 2; i++) {
                int ch  = tid + i * NTHREADS;
                int row = ch >> 4;
                int col = (ch & 15) * 8;
                cp_async16(smem_u32(&sB[s][row * SBKN_ST + col]),
                           Bg + (size_t)row * Nc + col);
            }
            cp_commit();
        };

        load_tiles(0, 0);

        for (int kt = 0; kt < kmax; kt++) {
            const int s = kt & 1;
            if (kt + 1 < kmax) { load_tiles(s ^ 1, kt + 1); cp_wait<1>(); }
            else               { cp_wait<0>(); }
            __syncthreads();

#pragma unroll
            for (int kk = 0; kk < BK; kk += 16) {
                uint32_t a[2][4];
#pragma unroll
                for (int i = 0; i < 2; i++) {
                    const bf16* p = &sA[s][(wm + i * 16 + (lane & 15)) * SA_ST
                                           + kk + (lane >> 4) * 8];
                    ldmx4(a[i][0], a[i][1], a[i][2], a[i][3], smem_u32(p));
                }
                uint32_t b[8][2];
#pragma unroll
                for (int j = 0; j < 8; j += 2) {
                    uint32_t r0, r1, r2, r3;
                    const bf16* p = &sB[s][(kk + (lane & 15)) * SBKN_ST
                                           + wn + j * 8 + (lane >> 4) * 8];
                    ldmx4t(r0, r1, r2, r3, smem_u32(p));
                    b[j][0] = r0; b[j][1] = r1; b[j + 1][0] = r2; b[j + 1][1] = r3;
                }
#pragma unroll
                for (int i = 0; i < 2; i++)
#pragma unroll
                    for (int j = 0; j < 8; j++)
                        mma16816_bf(acc[i][j], a[i], b[j]);
            }
            __syncthreads();
        }

        const int rbase = bm0 + wm + (lane >> 2);
        const int cbase = bn0 + wn + (lane & 3) * 2;
#pragma unroll
        for (int i = 0; i < 2; i++)
#pragma unroll
            for (int j = 0; j < 8; j++)
#pragma unroll
                for (int h = 0; h < 2; h++) {
                    const int r = rbase + i * 16 + h * 8;
                    const int c = cbase + j * 8;
                    const size_t o = (size_t)blockIdx.z * (Nt * Dc)
                                   + (size_t)r * Dc + c;
                    const float sc = scale[r];
                    float2 ov = make_float2(x[o] + acc[i][j][h * 2] * sc,
                                            x[o + 1] + acc[i][j][h * 2 + 1] * sc);
                    *reinterpret_cast<float2*>(g_y1 + o) = ov;
                }
        __syncthreads();
    }
}

// ---------------- MLP GEMM 1 (tensor, f16 acc) — cols [0, TEN_N1) --------------
__global__ void __launch_bounds__(NTHREADS, 2) mlp1_gemm_kernel(
    const float* __restrict__ bias)
{
    constexpr int K  = Dc;
    constexpr int KT = K / BK;

    const __half* __restrict__ A = g_x1h;
    const __half* __restrict__ B = g_W1h;

    __shared__ __align__(16) __half sA[2][BM * SA_ST];
    __shared__ __align__(16) __half sB[2][BN * SA_ST];

    const int tid  = threadIdx.x;
    const int wid  = tid >> 5;
    const int lane = tid & 31;
    const int bm0  = blockIdx.y * BM;
    const int bn0  = blockIdx.x * BN;
    const int wm   = (wid & 3) * 32;
    const int wn   = (wid >> 2) * 64;

    uint32_t acc[2][8][2];
#pragma unroll
    for (int i = 0; i < 2; i++)
#pragma unroll
        for (int j = 0; j < 8; j++) { acc[i][j][0] = 0u; acc[i][j][1] = 0u; }

    auto load_tiles = [&](int s, int kt) {
        const __half* Ag = A + (size_t)bm0 * K + (size_t)kt * BK;
#pragma unroll
        for (int i = 0; i < 2; i++) {
            int ch  = tid + i * NTHREADS;
            int row = ch >> 2;
            int col = (ch & 3) * 8;
            cp_async16(smem_u32(&sA[s][row * SA_ST + col]), Ag + (size_t)row * K + col);
        }
        const __half* Bg = B + (size_t)bn0 * K + (size_t)kt * BK;
#pragma unroll
        for (int i = 0; i < 2; i++) {
            int ch  = tid + i * NTHREADS;
            int row = ch >> 2;
            int col = (ch & 3) * 8;
            cp_async16(smem_u32(&sB[s][row * SA_ST + col]), Bg + (size_t)row * K + col);
        }
        cp_commit();
    };

    load_tiles(0, 0);

    for (int kt = 0; kt < KT; kt++) {
        const int s = kt & 1;
        if (kt + 1 < KT) { load_tiles(s ^ 1, kt + 1); cp_wait<1>(); }
        else             { cp_wait<0>(); }
        __syncthreads();

#pragma unroll
        for (int kk = 0; kk < BK; kk += 16) {
            uint32_t a[2][4];
#pragma unroll
            for (int i = 0; i < 2; i++) {
                const __half* p = &sA[s][(wm + i * 16 + (lane & 15)) * SA_ST
                                         + kk + (lane >> 4) * 8];
                ldmx4(a[i][0], a[i][1], a[i][2], a[i][3], smem_u32(p));
            }
            uint32_t b[8][2];
#pragma unroll
            for (int j = 0; j < 8; j += 2) {
                uint32_t r0, r1, r2, r3;
                int rr = wn + j * 8 + ((lane >> 4) << 3) + (lane & 7);
                int cc = kk + ((lane >> 3) & 1) * 8;
                const __half* p = &sB[s][rr * SA_ST + cc];
                ldmx4(r0, r1, r2, r3, smem_u32(p));
                b[j][0] = r0; b[j][1] = r1; b[j + 1][0] = r2; b[j + 1][1] = r3;
            }
#pragma unroll
            for (int i = 0; i < 2; i++)
#pragma unroll
                for (int j = 0; j < 8; j++)
                    mma16816_hf16(acc[i][j], a[i], b[j]);
        }
        __syncthreads();
    }

    const int rbase = bm0 + wm + (lane >> 2);
    const int cbase = bn0 + wn + (lane & 3) * 2;
#pragma unroll
    for (int i = 0; i < 2; i++) {
#pragma unroll
        for (int j = 0; j < 8; j++) {
#pragma unroll
            for (int h = 0; h < 2; h++) {
                const int r = rbase + i * 16 + h * 8;
                const int c = cbase + j * 8;
                __half2 hv = *reinterpret_cast<const __half2*>(&acc[i][j][h]);
                float v0 = __half2float(__low2half(hv))  + bias[c];
                float v1 = __half2float(__high2half(hv)) + bias[c + 1];
                __half2 ov = __floats2half2_rn(gelu_exact(v0), gelu_exact(v1));
                *reinterpret_cast<__half2*>(g_H + (size_t)r * Fc + c) = ov;
            }
        }
    }
}

// ---------------- MLP GEMM 2 (tensor, f32 acc, split-K=4) — cols [0, TEN_N2) ---
__global__ void __launch_bounds__(NTHREADS, 2) mlp2_gemm_kernel()
{
    constexpr int K  = Fc;
    constexpr int KS = Fc / KSPLIT;
    constexpr int KT = KS / BK;

    const int kofs = blockIdx.z * KS;
    const __half* __restrict__ A = g_H + kofs;
    const __half* __restrict__ B = g_W2h + kofs;

    __shared__ __align__(16) __half sA[2][BM * SA_ST];
    __shared__ __align__(16) __half sB[2][BN * SA_ST];

    const int tid  = threadIdx.x;
    const int wid  = tid >> 5;
    const int lane = tid & 31;
    const int bm0  = blockIdx.y * BM;
    const int bn0  = blockIdx.x * BN;
    const int wm   = (wid & 3) * 32;
    const int wn   = (wid >> 2) * 64;

    float acc[2][8][4];
#pragma unroll
    for (int i = 0; i < 2; i++)
#pragma unroll
        for (int j = 0; j < 8; j++)
#pragma unroll
            for (int q = 0; q < 4; q++) acc[i][j][q] = 0.0f;

    auto load_tiles = [&](int s, int kt) {
        const __half* Ag = A + (size_t)bm0 * K + (size_t)kt * BK;
#pragma unroll
        for (int i = 0; i < 2; i++) {
            int ch  = tid + i * NTHREADS;
            int row = ch >> 2;
            int col = (ch & 3) * 8;
            cp_async16(smem_u32(&sA[s][row * SA_ST + col]), Ag + (size_t)row * K + col);
        }
        const __half* Bg = B + (size_t)bn0 * K + (size_t)kt * BK;
#pragma unroll
        for (int i = 0; i < 2; i++) {
            int ch  = tid + i * NTHREADS;
            int row = ch >> 2;
            int col = (ch & 3) * 8;
            cp_async16(smem_u32(&sB[s][row * SA_ST + col]), Bg + (size_t)row * K + col);
        }
        cp_commit();
    };

    load_tiles(0, 0);

    for (int kt = 0; kt < KT; kt++) {
        const int s = kt & 1;
        if (kt + 1 < KT) { load_tiles(s ^ 1, kt + 1); cp_wait<1>(); }
        else             { cp_wait<0>(); }
        __syncthreads();

#pragma unroll
        for (int kk = 0; kk < BK; kk += 16) {
            uint32_t a[2][4];
#pragma unroll
            for (int i = 0; i < 2; i++) {
                const __half* p = &sA[s][(wm + i * 16 + (lane & 15)) * SA_ST
                                         + kk + (lane >> 4) * 8];
                ldmx4(a[i][0], a[i][1], a[i][2], a[i][3], smem_u32(p));
            }
            uint32_t b[8][2];
#pragma unroll
            for (int j = 0; j < 8; j += 2) {
                uint32_t r0, r1, r2, r3;
                int rr = wn + j * 8 + ((lane >> 4) << 3) + (lane & 7);
                int cc = kk + ((lane >> 3) & 1) * 8;
                const __half* p = &sB[s][rr * SA_ST + cc];
                ldmx4(r0, r1, r2, r3, smem_u32(p));
                b[j][0] = r0; b[j][1] = r1; b[j + 1][0] = r2; b[j + 1][1] = r3;
            }
#pragma unroll
            for (int i = 0; i < 2; i++)
#pragma unroll
                for (int j = 0; j < 8; j++)
                    mma16816_hf32(acc[i][j], a[i], b[j]);
        }
        __syncthreads();
    }

    float* __restrict__ P = g_p2 + (size_t)blockIdx.z * Mrows * Dc;
    const int rbase = bm0 + wm + (lane >> 2);
    const int cbase = bn0 + wn + (lane & 3) * 2;
#pragma unroll
    for (int i = 0; i < 2; i++)
#pragma unroll
        for (int j = 0; j < 8; j++)
#pragma unroll
            for (int h = 0; h < 2; h++) {
                const int r = rbase + i * 16 + h * 8;
                const int c = cbase + j * 8;
                const size_t o = (size_t)r * Dc + c;
                float2 ov = make_float2(acc[i][j][h * 2], acc[i][j][h * 2 + 1]);
                *reinterpret_cast<float2*>(P + o) = ov;
            }
}

// ---------------- SIMT GEMM slice (HFMA2 pipe, fp32 flush every 128 k) ---------
// WHICH=1: cols [TEN_N1, Fc) of GEMM1 -> gelu -> g_H
// WHICH=2: cols [TEN_N2, Dc) of GEMM2 (full K) -> fp32 -> g_p2 slice 0
template <int WHICH>
__global__ void __launch_bounds__(256) simt_gemm_kernel(const float* __restrict__ bias)
{
    constexpr int K    = (WHICH == 1) ? Dc : Fc;
    constexpr int KT   = K / 32;
    constexpr int COFS = (WHICH == 1) ? TEN_N1 : TEN_N2;

    const __half* __restrict__ A = (WHICH == 1) ? g_x1h : g_H;
    const __half* __restrict__ B = (WHICH == 1) ? g_W1h : g_W2h;

    __shared__ __align__(16) __half sA[2][32][68];
    __shared__ __align__(16) __half sB[2][32][68];

    const int tid = threadIdx.x;
    const int tx  = tid & 15;     // col group
    const int ty  = tid >> 4;     // row group
    const int m0  = blockIdx.y * 64;
    const int n0g = COFS + blockIdx.x * 64;

    const int lr = tid >> 2;          // 0..63
    const int lc = (tid & 3) * 8;     // k offset in tile

    const __half* Ag = A + (size_t)(m0  + lr) * K + lc;
    const __half* Bg = B + (size_t)(n0g + lr) * K + lc;

    float acc_f[4][4];
    __half2 acc_h[4][2];
    const __half2 hzero = __floats2half2_rn(0.0f, 0.0f);
#pragma unroll
    for (int i = 0; i < 4; i++) {
#pragma unroll
        for (int q = 0; q < 4; q++) acc_f[i][q] = 0.0f;
        acc_h[i][0] = hzero; acc_h[i][1] = hzero;
    }

    auto sts = [&](int s, const uint4& av, const uint4& bv) {
        const __half* ah = reinterpret_cast<const __half*>(&av);
        const __half* bh = reinterpret_cast<const __half*>(&bv);
#pragma unroll
        for (int j = 0; j < 8; j++) {
            sA[s][lc + j][lr] = ah[j];
            sB[s][lc + j][lr] = bh[j];
        }
    };

    uint4 ar = *reinterpret_cast<const uint4*>(Ag);
    uint4 br = *reinterpret_cast<const uint4*>(Bg);
    sts(0, ar, br);
    __syncthreads();

    for (int kt = 0; kt < KT; kt++) {
        const int s = kt & 1;
        if (kt + 1 < KT) {
            ar = *reinterpret_cast<const uint4*>(Ag + (size_t)(kt + 1) * 32);
            br = *reinterpret_cast<const uint4*>(Bg + (size_t)(kt + 1) * 32);
        }
#pragma unroll
        for (int kk = 0; kk < 32; kk++) {
            uint2 avv = *reinterpret_cast<const uint2*>(&sA[s][kk][4 * ty]);
            uint2 bvv = *reinterpret_cast<const uint2*>(&sB[s][kk][4 * tx]);
            __half2 a01 = *reinterpret_cast<const __half2*>(&avv.x);
            __half2 a23 = *reinterpret_cast<const __half2*>(&avv.y);
            __half2 b01 = *reinterpret_cast<const __half2*>(&bvv.x);
            __half2 b23 = *reinterpret_cast<const __half2*>(&bvv.y);
            __half2 aa;
            aa = __half2half2(__low2half(a01));
            acc_h[0][0] = __hfma2(aa, b01, acc_h[0][0]);
            acc_h[0][1] = __hfma2(aa, b23, acc_h[0][1]);
            aa = __half2half2(__high2half(a01));
            acc_h[1][0] = __hfma2(aa, b01, acc_h[1][0]);
            acc_h[1][1] = __hfma2(aa, b23, acc_h[1][1]);
            aa = __half2half2(__low2half(a23));
            acc_h[2][0] = __hfma2(aa, b01, acc_h[2][0]);
            acc_h[2][1] = __hfma2(aa, b23, acc_h[2][1]);
            aa = __half2half2(__high2half(a23));
            acc_h[3][0] = __hfma2(aa, b01, acc_h[3][0]);
            acc_h[3][1] = __hfma2(aa, b23, acc_h[3][1]);
        }
        // flush fp16 partials to fp32 every 128 k (4 tiles) — bounds fp16 error
        if ((kt & 3) == 3 || kt == KT - 1) {
#pragma unroll
            for (int i = 0; i < 4; i++) {
                float2 f0 = __half22float2(acc_h[i][0]);
                float2 f1 = __half22float2(acc_h[i][1]);
                acc_f[i][0] += f0.x; acc_f[i][1] += f0.y;
                acc_f[i][2] += f1.x; acc_f[i][3] += f1.y;
                acc_h[i][0] = hzero; acc_h[i][1] = hzero;
            }
        }
        if (kt + 1 < KT) sts(s ^ 1, ar, br);
        __syncthreads();
    }

    const int cg = n0g + 4 * tx;
#pragma unroll
    for (int i = 0; i < 4; i++) {
        const int r = m0 + 4 * ty + i;
        if constexpr (WHICH == 1) {
            float v0 = gelu_exact(acc_f[i][0] + bias[cg + 0]);
            float v1 = gelu_exact(acc_f[i][1] + bias[cg + 1]);
            float v2 = gelu_exact(acc_f[i][2] + bias[cg + 2]);
            float v3 = gelu_exact(acc_f[i][3] + bias[cg + 3]);
            __half2 o01 = __floats2half2_rn(v0, v1);
            __half2 o23 = __floats2half2_rn(v2, v3);
            uint2 pk;
            pk.x = *reinterpret_cast<uint32_t*>(&o01);
            pk.y = *reinterpret_cast<uint32_t*>(&o23);
            *reinterpret_cast<uint2*>(g_H + (size_t)r * Fc + cg) = pk;
        } else {
            float4 ov = make_float4(acc_f[i][0], acc_f[i][1], acc_f[i][2], acc_f[i][3]);
            *reinterpret_cast<float4*>(g_p2 + (size_t)r * Dc + cg) = ov;
        }
    }
}

// ---------------- LayerNorm 1 ---------------------------------------------------
__global__ void __launch_bounds__(256) ln1_kernel(
    const float* __restrict__ lw, const float* __restrict__ lb)
{
    const size_t row = blockIdx.x;
    const int t = threadIdx.x;

    float4 v = reinterpret_cast<const float4*>(g_y1 + row * Dc)[t];
    float s = v.x + v.y + v.z + v.w;
    float q = v.x * v.x + v.y * v.y + v.z * v.z + v.w * v.w;
#pragma unroll
    for (int o = 16; o > 0; o >>= 1) {
        s += __shfl_xor_sync(0xffffffffu, s, o);
        q += __shfl_xor_sync(0xffffffffu, q, o);
    }
    __shared__ float red[16];
    if ((t & 31) == 0) { red[t >> 5] = s; red[8 + (t >> 5)] = q; }
    __syncthreads();
    s = 0.0f; q = 0.0f;
#pragma unroll
    for (int i = 0; i < 8; i++) { s += red[i]; q += red[8 + i]; }

    const float mu  = s * (1.0f / Dc);
    const float inv = rsqrtf(q * (1.0f / Dc) - mu * mu + 1e-5f);
    const int c = t * 4;
    const float o0 = (v.x - mu) * inv * lw[c + 0] + lb[c + 0];
    const float o1 = (v.y - mu) * inv * lw[c + 1] + lb[c + 1];
    const float o2 = (v.z - mu) * inv * lw[c + 2] + lb[c + 2];
    const float o3 = (v.w - mu) * inv * lw[c + 3] + lb[c + 3];

    reinterpret_cast<float4*>(g_x1 + row * Dc)[t] = make_float4(o0, o1, o2, o3);
    __half2* ph = reinterpret_cast<__half2*>(g_x1h + row * Dc) + t * 2;
    ph[0] = __floats2half2_rn(o0, o1);
    ph[1] = __floats2half2_rn(o2, o3);
}

// ---------------- LayerNorm 2 (boundary-aware split-K reduce + LN -> out) -------
__global__ void __launch_bounds__(256) ln2_kernel(
    const float* __restrict__ b2, const float* __restrict__ scl,
    const float* __restrict__ lw, const float* __restrict__ lb,
    float* __restrict__ outp)
{
    const size_t row = blockIdx.x;
    const int t = threadIdx.x;
    const float sscal = scl[0];

    float4 xv = reinterpret_cast<const float4*>(g_x1 + row * Dc)[t];
    float4 bv = reinterpret_cast<const float4*>(b2)[t];
    float4 p;
    if (t < TEN_N2 / 4) {   // tensor split-K columns: sum 4 partial slices
        p = make_float4(0.f, 0.f, 0.f, 0.f);
#pragma unroll
        for (int z = 0; z < KSPLIT; z++) {
            float4 pz = reinterpret_cast<const float4*>(
                g_p2 + (size_t)z * Mrows * Dc + row * Dc)[t];
            p.x += pz.x; p.y += pz.y; p.z += pz.z; p.w += pz.w;
        }
    } else {                 // SIMT columns: full-K result in slice 0
        p = reinterpret_cast<const float4*>(g_p2 + row * Dc)[t];
    }
    float4 v;
    v.x = xv.x + sscal * (p.x + bv.x);
    v.y = xv.y + sscal * (p.y + bv.y);
    v.z = xv.z + sscal * (p.z + bv.z);
    v.w = xv.w + sscal * (p.w + bv.w);

    float s = v.x + v.y + v.z + v.w;
    float q = v.x * v.x + v.y * v.y + v.z * v.z + v.w * v.w;
#pragma unroll
    for (int o = 16; o > 0; o >>= 1) {
        s += __shfl_xor_sync(0xffffffffu, s, o);
        q += __shfl_xor_sync(0xffffffffu, q, o);
    }
    __shared__ float red[16];
    if ((t & 31) == 0) { red[t >> 5] = s; red[8 + (t >> 5)] = q; }
    __syncthreads();
    s = 0.0f; q = 0.0f;
#pragma unroll
    for (int i = 0; i < 8; i++) { s += red[i]; q += red[8 + i]; }

    const float mu  = s * (1.0f / Dc);
    const float inv = rsqrtf(q * (1.0f / Dc) - mu * mu + 1e-5f);
    const int c = t * 4;
    float4 ov;
    ov.x = (v.x - mu) * inv * lw[c + 0] + lb[c + 0];
    ov.y = (v.y - mu) * inv * lw[c + 1] + lb[c + 1];
    ov.z = (v.z - mu) * inv * lw[c + 2] + lb[c + 2];
    ov.w = (v.w - mu) * inv * lw[c + 3] + lb[c + 3];
    reinterpret_cast<float4*>(outp + row * Dc)[t] = ov;
}

// ---------------- launch --------------------------------------------------------
extern "C" void kernel_launch(void* const* d_in, const int* in_sizes, int n_in,
                              void* d_out, int out_size)
{
    const float* x       = (const float*)d_in[0];
    const float* weights = (const float*)d_in[1];
    const float* scale   = (const float*)d_in[2];
    const float* ln1w    = (const float*)d_in[3];
    const float* ln1b    = (const float*)d_in[4];
    const float* W1      = (const float*)d_in[5];
    const float* b1      = (const float*)d_in[6];
    const float* W2      = (const float*)d_in[7];
    const float* b2      = (const float*)d_in[8];
    const float* scalar  = (const float*)d_in[9];
    const float* ln2w    = (const float*)d_in[10];
    const float* ln2b    = (const float*)d_in[11];
    float* out = (float*)d_out;

    static cudaStream_t s2 = nullptr;
    static cudaEvent_t evFork = nullptr, evJoin = nullptr, evF2 = nullptr,
                       evT1 = nullptr, evS1 = nullptr, evS2 = nullptr;
    if (s2 == nullptr) {
        cudaStreamCreateWithFlags(&s2, cudaStreamNonBlocking);
        cudaEventCreateWithFlags(&evFork, cudaEventDisableTiming);
        cudaEventCreateWithFlags(&evJoin, cudaEventDisableTiming);
        cudaEventCreateWithFlags(&evF2,   cudaEventDisableTiming);
        cudaEventCreateWithFlags(&evT1,   cudaEventDisableTiming);
        cudaEventCreateWithFlags(&evS1,   cudaEventDisableTiming);
        cudaEventCreateWithFlags(&evS2,   cudaEventDisableTiming);
    }

    const int n4x = Bc * Nt * Dc / 4;
    const int n4w = Fc * Dc / 4;

    // fork: W1/W2 fp32->fp16 conversion on side stream
    cudaEventRecord(evFork, 0);
    cudaStreamWaitEvent(s2, evFork, 0);
    cvt_w_both_kernel<<<(2 * n4w + 255) / 256, 256, 0, s2>>>(W1, W2, n4w);
    cudaEventRecord(evJoin, s2);

    // main stream: conv chain
    cvt_x_kernel<<<(n4x + 255) / 256, 256>>>(x, n4x);
    buildT_kernel<<<(Nt * Nt) / 256, 256>>>(weights);
    conv_gemm_kernel<<<dim3(Dc / BN, 8, Bc), NTHREADS>>>(x, scale);
    ln1_kernel<<<Bc * Nt, 256>>>(ln1w, ln1b);

    // weights ready before any consumer on stream 0
    cudaStreamWaitEvent(0, evJoin, 0);

    // --- GEMM1 hybrid: tensor (28 col-blocks) || SIMT (512 cols on s2) ---
    cudaEventRecord(evF2, 0);
    cudaStreamWaitEvent(s2, evF2, 0);
    simt_gemm_kernel<1><<<dim3(SIMT_N1 / 64, Mrows / 64), 256, 0, s2>>>(b1);
    cudaEventRecord(evS1, s2);
    mlp1_gemm_kernel<<<dim3(TEN_N1 / BN, Mrows / BM), NTHREADS>>>(b1);
    cudaEventRecord(evT1, 0);

    // full H needed by both GEMM2 parts
    cudaStreamWaitEvent(0, evS1, 0);
    cudaStreamWaitEvent(s2, evT1, 0);

    // --- GEMM2 hybrid: tensor split-K (7 col-blocks) || SIMT (128 cols, full K) ---
    simt_gemm_kernel<2><<<dim3(SIMT_N2 / 64, Mrows / 64), 256, 0, s2>>>(nullptr);
    cudaEventRecord(evS2, s2);
    mlp2_gemm_kernel<<<dim3(TEN_N2 / BN, Mrows / BM, KSPLIT), NTHREADS>>>();
    cudaStreamWaitEvent(0, evS2, 0);

    ln2_kernel<<<Bc * Nt, 256>>>(b2, scalar, ln2w, ln2b, out);
}

// round 12
// speedup vs baseline: 1.3935x; 1.3935x over previous
#include <cuda_runtime.h>
#include <cuda_bf16.h>
#include <cuda_fp16.h>
#include <cstdint>

using bf16 = __nv_bfloat16;

#define DEVI __device__ __forceinline__

constexpr int Bc = 4;      // batch
constexpr int Nt = 2048;   // tokens
constexpr int Dc = 1024;   // model dim
constexpr int Fc = 4096;   // ffn dim
constexpr int Mrows = Bc * Nt;   // 8192
constexpr int KSPLIT = 4;        // GEMM2 split-K factor

constexpr int BM = 128, BN = 128, BK = 32;
constexpr int SA_ST   = BK + 8;    // 40
constexpr int SBKN_ST = BN + 8;    // 136
constexpr int NTHREADS = 256;

// GEMM1 big-tile config: 128x256 CTA tile, 64x64 warp tiles, f16 acc
constexpr int G1BN = 256;
constexpr int SMEM_G1 = 2 * BM * SA_ST * 2 + 2 * G1BN * SA_ST * 2;  // 61440

// ---------------- scratch ----------------------------------------------------
__device__ __align__(16) bf16   g_T[(size_t)Nt * Nt];
__device__ __align__(16) bf16   g_xb[(size_t)Bc * Nt * Dc];
__device__ __align__(16) float  g_y1[(size_t)Bc * Nt * Dc];
__device__ __align__(16) float  g_x1[(size_t)Bc * Nt * Dc];
__device__ __align__(16) __half g_x1h[(size_t)Bc * Nt * Dc];
__device__ __align__(16) __half g_W1h[(size_t)Fc * Dc];
__device__ __align__(16) __half g_W2h[(size_t)Dc * Fc];
__device__ __align__(16) __half g_H[(size_t)Bc * Nt * Fc];
__device__ __align__(16) float  g_p2[(size_t)KSPLIT * Mrows * Dc];  // split-K partials

// ---------------- PTX helpers -------------------------------------------------
DEVI uint32_t smem_u32(const void* p) {
    return static_cast<uint32_t>(__cvta_generic_to_shared(p));
}
DEVI void cp_async16(uint32_t sdst, const void* gsrc) {
    asm volatile("cp.async.cg.shared.global [%0], [%1], 16;\n" :: "r"(sdst), "l"(gsrc));
}
DEVI void cp_commit() { asm volatile("cp.async.commit_group;\n"); }
template <int N> DEVI void cp_wait() {
    asm volatile("cp.async.wait_group %0;\n" :: "n"(N));
}
DEVI void ldmx4(uint32_t& r0, uint32_t& r1, uint32_t& r2, uint32_t& r3, uint32_t a) {
    asm volatile("ldmatrix.sync.aligned.m8n8.x4.shared.b16 {%0,%1,%2,%3}, [%4];\n"
                 : "=r"(r0), "=r"(r1), "=r"(r2), "=r"(r3) : "r"(a));
}
DEVI void ldmx4t(uint32_t& r0, uint32_t& r1, uint32_t& r2, uint32_t& r3, uint32_t a) {
    asm volatile("ldmatrix.sync.aligned.m8n8.x4.trans.shared.b16 {%0,%1,%2,%3}, [%4];\n"
                 : "=r"(r0), "=r"(r1), "=r"(r2), "=r"(r3) : "r"(a));
}
DEVI void mma16816_bf(float c[4], const uint32_t a[4], const uint32_t b[2]) {
    asm volatile(
        "mma.sync.aligned.m16n8k16.row.col.f32.bf16.bf16.f32 "
        "{%0,%1,%2,%3}, {%4,%5,%6,%7}, {%8,%9}, {%0,%1,%2,%3};\n"
        : "+f"(c[0]), "+f"(c[1]), "+f"(c[2]), "+f"(c[3])
        : "r"(a[0]), "r"(a[1]), "r"(a[2]), "r"(a[3]), "r"(b[0]), "r"(b[1]));
}
DEVI void mma16816_hf32(float c[4], const uint32_t a[4], const uint32_t b[2]) {
    asm volatile(
        "mma.sync.aligned.m16n8k16.row.col.f32.f16.f16.f32 "
        "{%0,%1,%2,%3}, {%4,%5,%6,%7}, {%8,%9}, {%0,%1,%2,%3};\n"
        : "+f"(c[0]), "+f"(c[1]), "+f"(c[2]), "+f"(c[3])
        : "r"(a[0]), "r"(a[1]), "r"(a[2]), "r"(a[3]), "r"(b[0]), "r"(b[1]));
}
DEVI void mma16816_hf16(uint32_t c[2], const uint32_t a[4], const uint32_t b[2]) {
    asm volatile(
        "mma.sync.aligned.m16n8k16.row.col.f16.f16.f16.f16 "
        "{%0,%1}, {%2,%3,%4,%5}, {%6,%7}, {%0,%1};\n"
        : "+r"(c[0]), "+r"(c[1])
        : "r"(a[0]), "r"(a[1]), "r"(a[2]), "r"(a[3]), "r"(b[0]), "r"(b[1]));
}
DEVI float gelu_exact(float v) {
    return 0.5f * v * (1.0f + erff(v * 0.70710678118654752f));
}

// ---------------- prep kernels ----------------------------------------------
__global__ void cvt_x_kernel(const float* __restrict__ src, int n4)
{
    int i = blockIdx.x * blockDim.x + threadIdx.x;
    if (i < n4) {
        float4 v = reinterpret_cast<const float4*>(src)[i];
        __nv_bfloat162* d2 = reinterpret_cast<__nv_bfloat162*>(g_xb) + 2 * (size_t)i;
        d2[0] = __floats2bfloat162_rn(v.x, v.y);
        d2[1] = __floats2bfloat162_rn(v.z, v.w);
    }
}

__global__ void cvt_w_both_kernel(const float* __restrict__ W1,
                                  const float* __restrict__ W2, int n4each)
{
    int i = blockIdx.x * blockDim.x + threadIdx.x;
    const float* src;
    __half* dst;
    int idx;
    if (i < n4each)          { src = W1; dst = g_W1h; idx = i; }
    else if (i < 2 * n4each) { src = W2; dst = g_W2h; idx = i - n4each; }
    else return;
    float4 v = reinterpret_cast<const float4*>(src)[idx];
    __half2* d2 = reinterpret_cast<__half2*>(dst) + 2 * (size_t)idx;
    d2[0] = __floats2half2_rn(v.x, v.y);
    d2[1] = __floats2half2_rn(v.z, v.w);
}

__global__ void buildT_kernel(const float* __restrict__ w)
{
    int i = blockIdx.x * blockDim.x + threadIdx.x;
    int n = i >> 11;
    int m = i & (Nt - 1);
    float v = (m <= n) ? w[n - m] : 0.0f;
    g_T[i] = __float2bfloat16(v);
}

// ---------------- conv GEMM (bf16, f32 acc, PAIR-BALANCED triangular) ----------
__global__ void __launch_bounds__(NTHREADS, 2) conv_gemm_kernel(
    const float* __restrict__ x, const float* __restrict__ scale)
{
    constexpr int K = Nt;
    constexpr int Nc = Dc;

    const bf16* __restrict__ A  = g_T;
    const bf16* __restrict__ Bp = g_xb + (size_t)blockIdx.z * Nt * Dc;

    __shared__ __align__(16) bf16 sA[2][BM * SA_ST];
    __shared__ __align__(16) bf16 sB[2][BK * SBKN_ST];

    const int tid  = threadIdx.x;
    const int pair = blockIdx.y;
    const int bn0  = blockIdx.x * BN;
    const int wid  = tid >> 5;
    const int lane = tid & 31;
    const int wm   = (wid & 3) * 32;
    const int wn   = (wid >> 2) * 64;

#pragma unroll
    for (int half = 0; half < 2; half++) {
        const int ybm  = (half == 0) ? (15 - pair) : pair;
        const int bm0  = ybm * BM;
        const int kmax = 4 * (ybm + 1);

        float acc[2][8][4];
#pragma unroll
        for (int i = 0; i < 2; i++)
#pragma unroll
            for (int j = 0; j < 8; j++)
#pragma unroll
                for (int q = 0; q < 4; q++) acc[i][j][q] = 0.0f;

        auto load_tiles = [&](int s, int kt) {
            const bf16* Ag = A + (size_t)bm0 * K + (size_t)kt * BK;
#pragma unroll
            for (int i = 0; i < 2; i++) {
                int ch  = tid + i * NTHREADS;
                int row = ch >> 2;
                int col = (ch & 3) * 8;
                cp_async16(smem_u32(&sA[s][row * SA_ST + col]),
                           Ag + (size_t)row * K + col);
            }
            const bf16* Bg = Bp + (size_t)(kt * BK) * Nc + bn0;
#pragma unroll
            for (int i = 0; i < 2; i++) {
                int ch  = tid + i * NTHREADS;
                int row = ch >> 4;
                int col = (ch & 15) * 8;
                cp_async16(smem_u32(&sB[s][row * SBKN_ST + col]),
                           Bg + (size_t)row * Nc + col);
            }
            cp_commit();
        };

        load_tiles(0, 0);

        for (int kt = 0; kt < kmax; kt++) {
            const int s = kt & 1;
            if (kt + 1 < kmax) { load_tiles(s ^ 1, kt + 1); cp_wait<1>(); }
            else               { cp_wait<0>(); }
            __syncthreads();

#pragma unroll
            for (int kk = 0; kk < BK; kk += 16) {
                uint32_t a[2][4];
#pragma unroll
                for (int i = 0; i < 2; i++) {
                    const bf16* p = &sA[s][(wm + i * 16 + (lane & 15)) * SA_ST
                                           + kk + (lane >> 4) * 8];
                    ldmx4(a[i][0], a[i][1], a[i][2], a[i][3], smem_u32(p));
                }
                uint32_t b[8][2];
#pragma unroll
                for (int j = 0; j < 8; j += 2) {
                    uint32_t r0, r1, r2, r3;
                    const bf16* p = &sB[s][(kk + (lane & 15)) * SBKN_ST
                                           + wn + j * 8 + (lane >> 4) * 8];
                    ldmx4t(r0, r1, r2, r3, smem_u32(p));
                    b[j][0] = r0; b[j][1] = r1; b[j + 1][0] = r2; b[j + 1][1] = r3;
                }
#pragma unroll
                for (int i = 0; i < 2; i++)
#pragma unroll
                    for (int j = 0; j < 8; j++)
                        mma16816_bf(acc[i][j], a[i], b[j]);
            }
            __syncthreads();
        }

        const int rbase = bm0 + wm + (lane >> 2);
        const int cbase = bn0 + wn + (lane & 3) * 2;
#pragma unroll
        for (int i = 0; i < 2; i++)
#pragma unroll
            for (int j = 0; j < 8; j++)
#pragma unroll
                for (int h = 0; h < 2; h++) {
                    const int r = rbase + i * 16 + h * 8;
                    const int c = cbase + j * 8;
                    const size_t o = (size_t)blockIdx.z * (Nt * Dc)
                                   + (size_t)r * Dc + c;
                    const float sc = scale[r];
                    float2 ov = make_float2(x[o] + acc[i][j][h * 2] * sc,
                                            x[o + 1] + acc[i][j][h * 2 + 1] * sc);
                    *reinterpret_cast<float2*>(g_y1 + o) = ov;
                }
        __syncthreads();
    }
}

// ---------------- MLP GEMM 1 (128x256 tile, 64x64 warps, f16 acc) --------------
__global__ void __launch_bounds__(NTHREADS, 2) mlp1_gemm_kernel(
    const float* __restrict__ bias)
{
    constexpr int K  = Dc;
    constexpr int KT = K / BK;

    extern __shared__ __align__(16) __half smem[];
    __half* sA = smem;                            // [2][BM*SA_ST]
    __half* sB = smem + 2 * BM * SA_ST;           // [2][G1BN*SA_ST]

    const __half* __restrict__ A = g_x1h;
    const __half* __restrict__ B = g_W1h;

    const int tid  = threadIdx.x;
    const int wid  = tid >> 5;
    const int lane = tid & 31;
    const int bm0  = blockIdx.y * BM;
    const int bn0  = blockIdx.x * G1BN;
    const int wm   = (wid & 1) * 64;    // 2 warps along M
    const int wn   = (wid >> 1) * 64;   // 4 warps along N

    uint32_t acc[4][8][2];
#pragma unroll
    for (int i = 0; i < 4; i++)
#pragma unroll
        for (int j = 0; j < 8; j++) { acc[i][j][0] = 0u; acc[i][j][1] = 0u; }

    auto load_tiles = [&](int s, int kt) {
        const __half* Ag = A + (size_t)bm0 * K + (size_t)kt * BK;
        __half* sAs = sA + s * (BM * SA_ST);
#pragma unroll
        for (int i = 0; i < 2; i++) {              // 512 chunks
            int ch  = tid + i * NTHREADS;
            int row = ch >> 2;
            int col = (ch & 3) * 8;
            cp_async16(smem_u32(&sAs[row * SA_ST + col]), Ag + (size_t)row * K + col);
        }
        const __half* Bg = B + (size_t)bn0 * K + (size_t)kt * BK;
        __half* sBs = sB + s * (G1BN * SA_ST);
#pragma unroll
        for (int i = 0; i < 4; i++) {              // 1024 chunks
            int ch  = tid + i * NTHREADS;
            int row = ch >> 2;
            int col = (ch & 3) * 8;
            cp_async16(smem_u32(&sBs[row * SA_ST + col]), Bg + (size_t)row * K + col);
        }
        cp_commit();
    };

    load_tiles(0, 0);

    for (int kt = 0; kt < KT; kt++) {
        const int s = kt & 1;
        if (kt + 1 < KT) { load_tiles(s ^ 1, kt + 1); cp_wait<1>(); }
        else             { cp_wait<0>(); }
        __syncthreads();

        const __half* sAs = sA + s * (BM * SA_ST);
        const __half* sBs = sB + s * (G1BN * SA_ST);

#pragma unroll
        for (int kk = 0; kk < BK; kk += 16) {
            uint32_t a[4][4];
#pragma unroll
            for (int i = 0; i < 4; i++) {
                const __half* p = &sAs[(wm + i * 16 + (lane & 15)) * SA_ST
                                       + kk + (lane >> 4) * 8];
                ldmx4(a[i][0], a[i][1], a[i][2], a[i][3], smem_u32(p));
            }
            uint32_t b[8][2];
#pragma unroll
            for (int j = 0; j < 8; j += 2) {
                uint32_t r0, r1, r2, r3;
                int rr = wn + j * 8 + ((lane >> 4) << 3) + (lane & 7);
                int cc = kk + ((lane >> 3) & 1) * 8;
                const __half* p = &sBs[rr * SA_ST + cc];
                ldmx4(r0, r1, r2, r3, smem_u32(p));
                b[j][0] = r0; b[j][1] = r1; b[j + 1][0] = r2; b[j + 1][1] = r3;
            }
#pragma unroll
            for (int i = 0; i < 4; i++)
#pragma unroll
                for (int j = 0; j < 8; j++)
                    mma16816_hf16(acc[i][j], a[i], b[j]);
        }
        __syncthreads();
    }

    const int rbase = bm0 + wm + (lane >> 2);
    const int cbase = bn0 + wn + (lane & 3) * 2;
#pragma unroll
    for (int i = 0; i < 4; i++) {
#pragma unroll
        for (int j = 0; j < 8; j++) {
#pragma unroll
            for (int h = 0; h < 2; h++) {
                const int r = rbase + i * 16 + h * 8;
                const int c = cbase + j * 8;
                __half2 hv = *reinterpret_cast<const __half2*>(&acc[i][j][h]);
                float v0 = __half2float(__low2half(hv))  + bias[c];
                float v1 = __half2float(__high2half(hv)) + bias[c + 1];
                __half2 ov = __floats2half2_rn(gelu_exact(v0), gelu_exact(v1));
                *reinterpret_cast<__half2*>(g_H + (size_t)r * Fc + c) = ov;
            }
        }
    }
}

// ---------------- MLP GEMM 2 (f16 in, f32 acc, split-K=4) ----------------------
__global__ void __launch_bounds__(NTHREADS, 2) mlp2_gemm_kernel()
{
    constexpr int K  = Fc;
    constexpr int KS = Fc / KSPLIT;
    constexpr int KT = KS / BK;

    const int kofs = blockIdx.z * KS;
    const __half* __restrict__ A = g_H + kofs;
    const __half* __restrict__ B = g_W2h + kofs;

    __shared__ __align__(16) __half sA[2][BM * SA_ST];
    __shared__ __align__(16) __half sB[2][BN * SA_ST];

    const int tid  = threadIdx.x;
    const int wid  = tid >> 5;
    const int lane = tid & 31;
    const int bm0  = blockIdx.y * BM;
    const int bn0  = blockIdx.x * BN;
    const int wm   = (wid & 3) * 32;
    const int wn   = (wid >> 2) * 64;

    float acc[2][8][4];
#pragma unroll
    for (int i = 0; i < 2; i++)
#pragma unroll
        for (int j = 0; j < 8; j++)
#pragma unroll
            for (int q = 0; q < 4; q++) acc[i][j][q] = 0.0f;

    auto load_tiles = [&](int s, int kt) {
        const __half* Ag = A + (size_t)bm0 * K + (size_t)kt * BK;
#pragma unroll
        for (int i = 0; i < 2; i++) {
            int ch  = tid + i * NTHREADS;
            int row = ch >> 2;
            int col = (ch & 3) * 8;
            cp_async16(smem_u32(&sA[s][row * SA_ST + col]), Ag + (size_t)row * K + col);
        }
        const __half* Bg = B + (size_t)bn0 * K + (size_t)kt * BK;
#pragma unroll
        for (int i = 0; i < 2; i++) {
            int ch  = tid + i * NTHREADS;
            int row = ch >> 2;
            int col = (ch & 3) * 8;
            cp_async16(smem_u32(&sB[s][row * SA_ST + col]), Bg + (size_t)row * K + col);
        }
        cp_commit();
    };

    load_tiles(0, 0);

    for (int kt = 0; kt < KT; kt++) {
        const int s = kt & 1;
        if (kt + 1 < KT) { load_tiles(s ^ 1, kt + 1); cp_wait<1>(); }
        else             { cp_wait<0>(); }
        __syncthreads();

#pragma unroll
        for (int kk = 0; kk < BK; kk += 16) {
            uint32_t a[2][4];
#pragma unroll
            for (int i = 0; i < 2; i++) {
                const __half* p = &sA[s][(wm + i * 16 + (lane & 15)) * SA_ST
                                         + kk + (lane >> 4) * 8];
                ldmx4(a[i][0], a[i][1], a[i][2], a[i][3], smem_u32(p));
            }
            uint32_t b[8][2];
#pragma unroll
            for (int j = 0; j < 8; j += 2) {
                uint32_t r0, r1, r2, r3;
                int rr = wn + j * 8 + ((lane >> 4) << 3) + (lane & 7);
                int cc = kk + ((lane >> 3) & 1) * 8;
                const __half* p = &sB[s][rr * SA_ST + cc];
                ldmx4(r0, r1, r2, r3, smem_u32(p));
                b[j][0] = r0; b[j][1] = r1; b[j + 1][0] = r2; b[j + 1][1] = r3;
            }
#pragma unroll
            for (int i = 0; i < 2; i++)
#pragma unroll
                for (int j = 0; j < 8; j++)
                    mma16816_hf32(acc[i][j], a[i], b[j]);
        }
        __syncthreads();
    }

    float* __restrict__ P = g_p2 + (size_t)blockIdx.z * Mrows * Dc;
    const int rbase = bm0 + wm + (lane >> 2);
    const int cbase = bn0 + wn + (lane & 3) * 2;
#pragma unroll
    for (int i = 0; i < 2; i++)
#pragma unroll
        for (int j = 0; j < 8; j++)
#pragma unroll
            for (int h = 0; h < 2; h++) {
                const int r = rbase + i * 16 + h * 8;
                const int c = cbase + j * 8;
                const size_t o = (size_t)r * Dc + c;
                float2 ov = make_float2(acc[i][j][h * 2], acc[i][j][h * 2 + 1]);
                *reinterpret_cast<float2*>(P + o) = ov;
            }
}

// ---------------- LayerNorm 1 ---------------------------------------------------
__global__ void __launch_bounds__(256) ln1_kernel(
    const float* __restrict__ lw, const float* __restrict__ lb)
{
    const size_t row = blockIdx.x;
    const int t = threadIdx.x;

    float4 v = reinterpret_cast<const float4*>(g_y1 + row * Dc)[t];
    float s = v.x + v.y + v.z + v.w;
    float q = v.x * v.x + v.y * v.y + v.z * v.z + v.w * v.w;
#pragma unroll
    for (int o = 16; o > 0; o >>= 1) {
        s += __shfl_xor_sync(0xffffffffu, s, o);
        q += __shfl_xor_sync(0xffffffffu, q, o);
    }
    __shared__ float red[16];
    if ((t & 31) == 0) { red[t >> 5] = s; red[8 + (t >> 5)] = q; }
    __syncthreads();
    s = 0.0f; q = 0.0f;
#pragma unroll
    for (int i = 0; i < 8; i++) { s += red[i]; q += red[8 + i]; }

    const float mu  = s * (1.0f / Dc);
    const float inv = rsqrtf(q * (1.0f / Dc) - mu * mu + 1e-5f);
    const int c = t * 4;
    const float o0 = (v.x - mu) * inv * lw[c + 0] + lb[c + 0];
    const float o1 = (v.y - mu) * inv * lw[c + 1] + lb[c + 1];
    const float o2 = (v.z - mu) * inv * lw[c + 2] + lb[c + 2];
    const float o3 = (v.w - mu) * inv * lw[c + 3] + lb[c + 3];

    reinterpret_cast<float4*>(g_x1 + row * Dc)[t] = make_float4(o0, o1, o2, o3);
    __half2* ph = reinterpret_cast<__half2*>(g_x1h + row * Dc) + t * 2;
    ph[0] = __floats2half2_rn(o0, o1);
    ph[1] = __floats2half2_rn(o2, o3);
}

// ---------------- LayerNorm 2 (split-K reduce + residual + LN -> out) -----------
__global__ void __launch_bounds__(256) ln2_kernel(
    const float* __restrict__ b2, const float* __restrict__ scl,
    const float* __restrict__ lw, const float* __restrict__ lb,
    float* __restrict__ outp)
{
    const size_t row = blockIdx.x;
    const int t = threadIdx.x;
    const float sscal = scl[0];

    float4 xv = reinterpret_cast<const float4*>(g_x1 + row * Dc)[t];
    float4 bv = reinterpret_cast<const float4*>(b2)[t];
    float4 p  = make_float4(0.f, 0.f, 0.f, 0.f);
#pragma unroll
    for (int z = 0; z < KSPLIT; z++) {
        float4 pz = reinterpret_cast<const float4*>(
            g_p2 + (size_t)z * Mrows * Dc + row * Dc)[t];
        p.x += pz.x; p.y += pz.y; p.z += pz.z; p.w += pz.w;
    }
    float4 v;
    v.x = xv.x + sscal * (p.x + bv.x);
    v.y = xv.y + sscal * (p.y + bv.y);
    v.z = xv.z + sscal * (p.z + bv.z);
    v.w = xv.w + sscal * (p.w + bv.w);

    float s = v.x + v.y + v.z + v.w;
    float q = v.x * v.x + v.y * v.y + v.z * v.z + v.w * v.w;
#pragma unroll
    for (int o = 16; o > 0; o >>= 1) {
        s += __shfl_xor_sync(0xffffffffu, s, o);
        q += __shfl_xor_sync(0xffffffffu, q, o);
    }
    __shared__ float red[16];
    if ((t & 31) == 0) { red[t >> 5] = s; red[8 + (t >> 5)] = q; }
    __syncthreads();
    s = 0.0f; q = 0.0f;
#pragma unroll
    for (int i = 0; i < 8; i++) { s += red[i]; q += red[8 + i]; }

    const float mu  = s * (1.0f / Dc);
    const float inv = rsqrtf(q * (1.0f / Dc) - mu * mu + 1e-5f);
    const int c = t * 4;
    float4 ov;
    ov.x = (v.x - mu) * inv * lw[c + 0] + lb[c + 0];
    ov.y = (v.y - mu) * inv * lw[c + 1] + lb[c + 1];
    ov.z = (v.z - mu) * inv * lw[c + 2] + lb[c + 2];
    ov.w = (v.w - mu) * inv * lw[c + 3] + lb[c + 3];
    reinterpret_cast<float4*>(outp + row * Dc)[t] = ov;
}

// ---------------- launch --------------------------------------------------------
extern "C" void kernel_launch(void* const* d_in, const int* in_sizes, int n_in,
                              void* d_out, int out_size)
{
    const float* x       = (const float*)d_in[0];
    const float* weights = (const float*)d_in[1];
    const float* scale   = (const float*)d_in[2];
    const float* ln1w    = (const float*)d_in[3];
    const float* ln1b    = (const float*)d_in[4];
    const float* W1      = (const float*)d_in[5];
    const float* b1      = (const float*)d_in[6];
    const float* W2      = (const float*)d_in[7];
    const float* b2      = (const float*)d_in[8];
    const float* scalar  = (const float*)d_in[9];
    const float* ln2w    = (const float*)d_in[10];
    const float* ln2b    = (const float*)d_in[11];
    float* out = (float*)d_out;

    static cudaStream_t s2 = nullptr;
    static cudaEvent_t evFork = nullptr, evJoin = nullptr;
    if (s2 == nullptr) {
        cudaStreamCreateWithFlags(&s2, cudaStreamNonBlocking);
        cudaEventCreateWithFlags(&evFork, cudaEventDisableTiming);
        cudaEventCreateWithFlags(&evJoin, cudaEventDisableTiming);
        cudaFuncSetAttribute(mlp1_gemm_kernel,
                             cudaFuncAttributeMaxDynamicSharedMemorySize, SMEM_G1);
    }

    const int n4x = Bc * Nt * Dc / 4;
    const int n4w = Fc * Dc / 4;

    // fork: W1/W2 fp32->fp16 conversion on side stream
    cudaEventRecord(evFork, 0);
    cudaStreamWaitEvent(s2, evFork, 0);
    cvt_w_both_kernel<<<(2 * n4w + 255) / 256, 256, 0, s2>>>(W1, W2, n4w);
    cudaEventRecord(evJoin, s2);

    // main stream: conv chain
    cvt_x_kernel<<<(n4x + 255) / 256, 256>>>(x, n4x);
    buildT_kernel<<<(Nt * Nt) / 256, 256>>>(weights);
    conv_gemm_kernel<<<dim3(Dc / BN, 8, Bc), NTHREADS>>>(x, scale);
    ln1_kernel<<<Bc * Nt, 256>>>(ln1w, ln1b);

    cudaStreamWaitEvent(0, evJoin, 0);

    // MLP up + GELU: 128x256 tile, f16 acc, dynamic smem
    mlp1_gemm_kernel<<<dim3(Fc / G1BN, Mrows / BM), NTHREADS, SMEM_G1>>>(b1);
    // MLP down, split-K=4 partials
    mlp2_gemm_kernel<<<dim3(Dc / BN, Mrows / BM, KSPLIT), NTHREADS>>>();
    // LN2: reduce + bias + scalar residual + LN -> output
    ln2_kernel<<<Bc * Nt, 256>>>(b2, scalar, ln2w, ln2b, out);
}